// round 17
// baseline (speedup 1.0000x reference)
#include <cuda_runtime.h>
#include <cstdint>

// Problem constants
#define B_ 8
#define V_ 49
#define H_ 128
#define W_ 128
#define F_ 64

// out[b,v,h,f] = sum_w lfi[b,v,h,w] + W * h_mask[b,f,h]
//
// Champion geometry (block = one (b,h) pair, 1024 blocks, smem mask staging,
// deferred sync, evict-first stores) restructured as a prefetch-led pipeline:
//   t=0: all 49 row prefetches to L2 (no MSHR cost), then 3 iterations of
//   16 demand rows (+1 tail row). Iterations 1-3 have >=1 iteration of lead,
//   so their loads should be L2 hits (~130ns) instead of DRAM (~600ns),
//   lifting the per-SM in-flight-line cap's effective bandwidth ~2.4x.

__device__ __forceinline__ void prefetch_l2(const void* p, uint32_t bytes) {
    asm volatile("cp.async.bulk.prefetch.L2.global [%0], %1;"
                 :: "l"(p), "r"(bytes) : "memory");
}
__device__ __forceinline__ unsigned long long pol_evict_first() {
    unsigned long long p;
    asm("createpolicy.fractional.L2::evict_first.b64 %0, 1.0;" : "=l"(p));
    return p;
}
__device__ __forceinline__ void st_stream2(float2* a, float x, float y,
                                           unsigned long long pol) {
    asm volatile("st.global.L2::cache_hint.v2.f32 [%0], {%1,%2}, %3;"
                 :: "l"(a), "f"(x), "f"(y), "l"(pol) : "memory");
}
__device__ __forceinline__ float rowsum(const float4 v) {
    return (v.x + v.y) + (v.z + v.w);
}
__device__ __forceinline__ float bfly(float s) {
    #pragma unroll
    for (int o = 16; o > 0; o >>= 1)
        s += __shfl_xor_sync(0xffffffffu, s, o);
    return s;
}

__global__ void __launch_bounds__(256, 7)
depth_cue_kernel(const float* __restrict__ lfi,
                 const float* __restrict__ h_mask,
                 float2* __restrict__ out2) {
    __shared__ float m_s[F_];

    const int tid  = threadIdx.x;
    const int wid  = tid >> 5;
    const int lane = tid & 31;

    const int pair = blockIdx.x;          // b*128 + h
    const int b = pair >> 7;
    const int h = pair & (H_ - 1);

    // 0) Fire all 49 row prefetches for this block (tid < 49, one 512B row each).
    //    No register/MSHR cost; gives iterations 1..3 a full-iteration lead.
    const float* plane = lfi + ((size_t)(b * V_ * H_) + h) * W_;  // v-stride H*W
    if (tid < V_) prefetch_l2(plane + (size_t)tid * (H_ * W_), W_ * 4);

    // 1) Scattered mask gather (warps 0,1), overlapped with iter-0 loads
    float mval = 0.0f;
    if (tid < F_) {
        mval = (float)W_ * __ldg(&h_mask[((b << 6) + tid) * H_ + h]);
    }

    const unsigned long long pf = pol_evict_first();
    const float4* lfi4 = (const float4*)lfi;
    const size_t r4 = ((size_t)(b * V_ * H_) + h) * 32 + lane;  // row v: r4 + v*4096

    // ---- Iteration 0: v = 2*wid, 2*wid+1 (rows 0..15) ----
    const float4 x0 = lfi4[r4 + (size_t)(2 * wid + 0) * 4096];
    const float4 y0 = lfi4[r4 + (size_t)(2 * wid + 1) * 4096];
    if (tid < F_) m_s[tid] = mval;        // park mask (overlaps load waits)
    float s0 = bfly(rowsum(x0));
    float s1 = bfly(rowsum(y0));
    __syncthreads();                      // mask ready; only barrier in kernel
    const float2 m = ((const float2*)m_s)[lane];
    st_stream2(&out2[r4 + (size_t)(2 * wid + 0) * 4096], s0 + m.x, s0 + m.y, pf);
    st_stream2(&out2[r4 + (size_t)(2 * wid + 1) * 4096], s1 + m.x, s1 + m.y, pf);

    // ---- Iterations 1,2: v = 16k + 2*wid, +1 (rows 16..47) — prefetched ----
    #pragma unroll
    for (int k = 1; k < 3; k++) {
        const size_t v0 = (size_t)(16 * k + 2 * wid);
        const float4 x = lfi4[r4 + (v0 + 0) * 4096];
        const float4 y = lfi4[r4 + (v0 + 1) * 4096];
        const float t0 = bfly(rowsum(x));
        const float t1 = bfly(rowsum(y));
        st_stream2(&out2[r4 + (v0 + 0) * 4096], t0 + m.x, t0 + m.y, pf);
        st_stream2(&out2[r4 + (v0 + 1) * 4096], t1 + m.x, t1 + m.y, pf);
    }

    // ---- Tail: v = 48 (warp 0 only) ----
    if (wid == 0) {
        const float4 x = lfi4[r4 + (size_t)48 * 4096];
        const float t = bfly(rowsum(x));
        st_stream2(&out2[r4 + (size_t)48 * 4096], t + m.x, t + m.y, pf);
    }
}

extern "C" void kernel_launch(void* const* d_in, const int* in_sizes, int n_in,
                              void* d_out, int out_size) {
    // Identify inputs by element count (robust to ordering):
    //   lfi    : B*V*H*W = 6,422,528
    //   f_maps : B*H*W*F = 8,388,608 (dead input — never touched)
    //   h_mask : B*F*H   = 65,536
    const float* lfi = nullptr;
    const float* h_mask = nullptr;
    for (int i = 0; i < n_in; i++) {
        if (in_sizes[i] == B_ * V_ * H_ * W_) lfi = (const float*)d_in[i];
        else if (in_sizes[i] == B_ * F_ * H_) h_mask = (const float*)d_in[i];
    }

    // 1024 blocks (one per (b,h) pair), 256 threads (8 warps)
    depth_cue_kernel<<<B_ * H_, 256>>>(lfi, h_mask, (float2*)d_out);
}